// round 5
// baseline (speedup 1.0000x reference)
#include <cuda_runtime.h>
#include <cstdint>

#define DIMN 2048
#define BTOK 16384
#define HOFF 4096
#define QKV3 6144

#define MT 128          // CTA tile M
#define NTCTA 128       // CTA tile N
#define KT 32           // K chunk
#define NSTG 4
#define SK 36           // smem row stride in floats (32 + 4 pad)
#define ASTG_F (MT * SK)            // floats per A stage (4608)
#define STGB ((ASTG_F * 2) * 4)     // stage bytes: A+B = 36864
#define SMEM_DYN (NSTG * STGB)      // 147456

// Scratch (allocation-free per harness rules)
__device__ float g_WT[(size_t)DIMN * DIMN];   // (Wv@Wp)^T, row-major [j][k]
__device__ float g_WPT[(size_t)DIMN * DIMN];  // Wp^T, row-major [j][h]
__device__ float g_CB[DIMN];                  // fused bias

// ---------------- helpers ----------------
__device__ __forceinline__ uint32_t smem_u32(const void* p) {
    uint32_t a;
    asm("{ .reg .u64 t; cvta.to.shared.u64 t, %1; cvt.u32.u64 %0, t; }"
        : "=r"(a) : "l"(p));
    return a;
}
__device__ __forceinline__ uint32_t rna_u32(float x) {
    uint32_t r;
    asm("cvt.rna.tf32.f32 %0, %1;" : "=r"(r) : "f"(x));
    return r;
}
__device__ __forceinline__ void cp16(uint32_t dst, const void* src) {
    asm volatile("cp.async.cg.shared.global [%0], [%1], 16;"
                 :: "r"(dst), "l"(src) : "memory");
}
#define CP_COMMIT() asm volatile("cp.async.commit_group;" ::: "memory")
#define CP_WAIT2()  asm volatile("cp.async.wait_group 2;" ::: "memory")

__device__ __forceinline__ void mma_tf32(float& d0, float& d1, float& d2, float& d3,
                                         uint32_t a0, uint32_t a1, uint32_t a2, uint32_t a3,
                                         uint32_t b0, uint32_t b1) {
    asm volatile(
        "mma.sync.aligned.m16n8k8.row.col.f32.tf32.tf32.f32 "
        "{%0,%1,%2,%3}, {%4,%5,%6,%7}, {%8,%9}, {%0,%1,%2,%3};"
        : "+f"(d0), "+f"(d1), "+f"(d2), "+f"(d3)
        : "r"(a0), "r"(a1), "r"(a2), "r"(a3), "r"(b0), "r"(b1));
}

// ---------------- prepass kernels ----------------
// WPT[j, h] = w_proj[h, j]
__global__ void transpose_kernel(const float* __restrict__ in,
                                 float* __restrict__ out, int n) {
    __shared__ float t[32][33];
    int x = blockIdx.x * 32 + threadIdx.x;
    int y0 = blockIdx.y * 32;
    for (int i = threadIdx.y; i < 32; i += 8)
        t[i][threadIdx.x] = in[(size_t)(y0 + i) * n + x];
    __syncthreads();
    int xo = blockIdx.y * 32 + threadIdx.x;
    int yo0 = blockIdx.x * 32;
    for (int i = threadIdx.y; i < 32; i += 8)
        out[(size_t)(yo0 + i) * n + xo] = t[threadIdx.x][i];
}

// CB[j] = b_proj[j] + sum_h b_qkv[4096+h] * w_proj[h, j]
__global__ void bias_kernel(const float* __restrict__ b_qkv,
                            const float* __restrict__ w_proj,
                            const float* __restrict__ b_proj,
                            float* __restrict__ cb) {
    int j = blockIdx.x * blockDim.x + threadIdx.x;
    float acc = b_proj[j];
#pragma unroll 8
    for (int h = 0; h < DIMN; ++h)
        acc += b_qkv[HOFF + h] * w_proj[(size_t)h * DIMN + j];
    cb[j] = acc;
}

// ---------------- tf32 mma.sync GEMM ----------------
// out[m, n] = sum_k A[m, k] * B[n, k] (+ bias[n])
// A: lda-strided row-major [M][K]; B: ldb-strided row-major [N][K].
// Tile 128x128, 8 warps (32x64 each), K chunks of 32, 4-stage cp.async ring.
__device__ __forceinline__ void fill_stage(uint32_t sa,
                                           const float* __restrict__ A,
                                           const float* __restrict__ B,
                                           int m0, int n0, int k0,
                                           int lda, int ldb, int tid) {
    const float* abase = A + (size_t)m0 * lda + k0;
#pragma unroll
    for (int i = tid; i < MT * (KT / 4); i += 256) {     // 1024 float4
        int row = i >> 3, cw = i & 7;
        cp16(sa + (uint32_t)(row * (SK * 4) + cw * 16),
             abase + (size_t)row * lda + cw * 4);
    }
    const float* bbase = B + (size_t)n0 * ldb + k0;
    uint32_t sbb = sa + ASTG_F * 4;
#pragma unroll
    for (int i = tid; i < NTCTA * (KT / 4); i += 256) {  // 1024 float4
        int row = i >> 3, cw = i & 7;
        cp16(sbb + (uint32_t)(row * (SK * 4) + cw * 16),
             bbase + (size_t)row * ldb + cw * 4);
    }
}

__global__ void __launch_bounds__(256, 1)
gemm_tf32_kernel(const float* __restrict__ A, const float* __restrict__ B,
                 float* __restrict__ out, const float* __restrict__ bias,
                 int K, int lda, int ldb, int ldo) {
    extern __shared__ __align__(16) float smem[];
    const uint32_t sb = smem_u32(smem);

    const int tid = threadIdx.x;
    const int wid = tid >> 5;
    const int lane = tid & 31;
    const int gid = lane >> 2;       // 0..7
    const int tig = lane & 3;        // 0..3
    const int m0 = blockIdx.y * MT;
    const int n0 = blockIdx.x * NTCTA;
    const int moff = (wid & 3) * 32; // warp M offset in tile
    const int noff = (wid >> 2) * 64;// warp N offset in tile

    float acc[2][8][4];
#pragma unroll
    for (int mt = 0; mt < 2; ++mt)
#pragma unroll
        for (int nt = 0; nt < 8; ++nt)
#pragma unroll
            for (int r = 0; r < 4; ++r) acc[mt][nt][r] = 0.0f;

    const int niter = K / KT;

    // prologue: fill stages 0..2
    for (int c = 0; c < NSTG - 1; ++c) {
        fill_stage(sb + c * STGB, A, B, m0, n0, c * KT, lda, ldb, tid);
        CP_COMMIT();
    }

    for (int it = 0; it < niter; ++it) {
        CP_WAIT2();          // stage it resident (3+it committed, <=2 pending)
        __syncthreads();     // visible to all; prev compute done

        const int c = it + NSTG - 1;
        if (c < niter)
            fill_stage(sb + (c & (NSTG - 1)) * STGB, A, B, m0, n0, c * KT,
                       lda, ldb, tid);
        CP_COMMIT();

        const float* sA = smem + (size_t)(it & (NSTG - 1)) * (STGB / 4);
        const float* sB = sA + ASTG_F;

#pragma unroll
        for (int kk = 0; kk < KT; kk += 8) {
            uint32_t a[2][4];
#pragma unroll
            for (int mt = 0; mt < 2; ++mt) {
                const float* ap = sA + (size_t)(moff + mt * 16 + gid) * SK + kk + tig;
                a[mt][0] = rna_u32(ap[0]);
                a[mt][1] = rna_u32(ap[8 * SK]);
                a[mt][2] = rna_u32(ap[4]);
                a[mt][3] = rna_u32(ap[8 * SK + 4]);
            }
            uint32_t b[8][2];
#pragma unroll
            for (int nt = 0; nt < 8; ++nt) {
                const float* bp = sB + (size_t)(noff + nt * 8 + gid) * SK + kk + tig;
                b[nt][0] = rna_u32(bp[0]);
                b[nt][1] = rna_u32(bp[4]);
            }
#pragma unroll
            for (int mt = 0; mt < 2; ++mt)
#pragma unroll
                for (int nt = 0; nt < 8; ++nt)
                    mma_tf32(acc[mt][nt][0], acc[mt][nt][1],
                             acc[mt][nt][2], acc[mt][nt][3],
                             a[mt][0], a[mt][1], a[mt][2], a[mt][3],
                             b[nt][0], b[nt][1]);
        }
    }

    // epilogue: direct global stores (+bias)
    float2 bb[8];
#pragma unroll
    for (int nt = 0; nt < 8; ++nt) {
        if (bias) {
            bb[nt] = *reinterpret_cast<const float2*>(
                bias + n0 + noff + nt * 8 + tig * 2);
        } else {
            bb[nt].x = 0.0f; bb[nt].y = 0.0f;
        }
    }
#pragma unroll
    for (int mt = 0; mt < 2; ++mt) {
        const int r0 = m0 + moff + mt * 16 + gid;
#pragma unroll
        for (int nt = 0; nt < 8; ++nt) {
            const int col = n0 + noff + nt * 8 + tig * 2;
            float2 v0, v1;
            v0.x = acc[mt][nt][0] + bb[nt].x;
            v0.y = acc[mt][nt][1] + bb[nt].y;
            v1.x = acc[mt][nt][2] + bb[nt].x;
            v1.y = acc[mt][nt][3] + bb[nt].y;
            *reinterpret_cast<float2*>(out + (size_t)r0 * ldo + col) = v0;
            *reinterpret_cast<float2*>(out + (size_t)(r0 + 8) * ldo + col) = v1;
        }
    }
}

// ---------------- host ----------------
extern "C" void kernel_launch(void* const* d_in, const int* in_sizes, int n_in,
                              void* d_out, int out_size) {
    (void)in_sizes; (void)n_in; (void)out_size;
    const float* x     = (const float*)d_in[0];
    const float* wqkv  = (const float*)d_in[1];
    const float* bqkv  = (const float*)d_in[2];
    const float* wproj = (const float*)d_in[3];
    const float* bproj = (const float*)d_in[4];
    float* out = (float*)d_out;

    float *WT, *WPT, *CB;
    cudaGetSymbolAddress((void**)&WT,  g_WT);
    cudaGetSymbolAddress((void**)&WPT, g_WPT);
    cudaGetSymbolAddress((void**)&CB,  g_CB);

    cudaFuncSetAttribute(gemm_tf32_kernel,
                         cudaFuncAttributeMaxDynamicSharedMemorySize, SMEM_DYN);

    // WPT[j,h] = Wp[h,j]
    transpose_kernel<<<dim3(64, 64), dim3(32, 8)>>>(wproj, WPT, DIMN);
    // CB[j] = bp[j] + sum_h bv[h] * Wp[h,j]
    bias_kernel<<<8, 256>>>(bqkv, wproj, bproj, CB);

    // WT[j,k] = sum_h WPT[j,h] * Wv[k,h];  Wv[k,h] = wqkv[k, 4096+h]
    gemm_tf32_kernel<<<dim3(DIMN / NTCTA, DIMN / MT), 256, SMEM_DYN>>>(
        WPT, wqkv + HOFF, WT, nullptr, DIMN, DIMN, QKV3, DIMN);

    // out[b,j] = sum_k x[b,k] * WT[j,k] + CB[j]
    gemm_tf32_kernel<<<dim3(DIMN / NTCTA, BTOK / MT), 256, SMEM_DYN>>>(
        x, WT, out, CB, DIMN, DIMN, DIMN, DIMN);
}

// round 6
// speedup vs baseline: 1.2050x; 1.2050x over previous
#include <cuda_runtime.h>
#include <cstdint>

#define DIMN 2048
#define BTOK 16384
#define HOFF 4096
#define QKV3 6144

#define MT 128
#define NTCTA 128
#define KT 32
#define NSTG 3
#define ABYTES (MT * KT * 4)       /* 16384 */
#define STGB (2 * ABYTES)          /* 32768: A + B stage */
#define SMEM_DYN (NSTG * STGB)     /* 98304 -> 2 CTAs/SM */

// Scratch (allocation-free per harness rules); all K-permuted + tf32-rounded
__device__ float g_XRP[(size_t)BTOK * DIMN];   // rna+perm(x)           128 MB
__device__ float g_WPT[(size_t)DIMN * DIMN];   // rna+perm(Wp^T)         16 MB
__device__ float g_WVR[(size_t)DIMN * DIMN];   // rna+perm(Wv slice)     16 MB
__device__ float g_WTraw[(size_t)DIMN * DIMN]; // (Wv@Wp)^T fp32         16 MB
__device__ float g_WTP[(size_t)DIMN * DIMN];   // rna+perm(WTraw)        16 MB
__device__ float g_CB[DIMN];                   // fused bias

// ---------------- helpers ----------------
__device__ __forceinline__ uint32_t smem_u32(const void* p) {
    uint32_t a;
    asm("{ .reg .u64 t; cvta.to.shared.u64 t, %1; cvt.u32.u64 %0, t; }"
        : "=r"(a) : "l"(p));
    return a;
}
__device__ __forceinline__ float rna_f(float x) {
    uint32_t r;
    asm("cvt.rna.tf32.f32 %0, %1;" : "=r"(r) : "f"(x));
    return __uint_as_float(r);
}
__device__ __forceinline__ void cp16(uint32_t dst, const void* src) {
    asm volatile("cp.async.cg.shared.global [%0], [%1], 16;"
                 :: "r"(dst), "l"(src) : "memory");
}
#define CP_COMMIT() asm volatile("cp.async.commit_group;" ::: "memory")
#define CP_WAIT1()  asm volatile("cp.async.wait_group 1;" ::: "memory")

__device__ __forceinline__ uint4 lds128(uint32_t a) {
    uint4 v;
    asm volatile("ld.shared.v4.b32 {%0,%1,%2,%3}, [%4];"
                 : "=r"(v.x), "=r"(v.y), "=r"(v.z), "=r"(v.w) : "r"(a));
    return v;
}
__device__ __forceinline__ void mma_tf32(float* d,
                                         uint32_t a0, uint32_t a1, uint32_t a2, uint32_t a3,
                                         uint32_t b0, uint32_t b1) {
    asm volatile(
        "mma.sync.aligned.m16n8k8.row.col.f32.tf32.tf32.f32 "
        "{%0,%1,%2,%3}, {%4,%5,%6,%7}, {%8,%9}, {%0,%1,%2,%3};"
        : "+f"(d[0]), "+f"(d[1]), "+f"(d[2]), "+f"(d[3])
        : "r"(a0), "r"(a1), "r"(a2), "r"(a3), "r"(b0), "r"(b1));
}

// ---------------- prepass kernels ----------------
// dst[r][perm(c)] = rna(src[r][c]); 16-group perm: phys 4t+j <- logical t+4j
__global__ void permute_rna_kernel(const float* __restrict__ src,
                                   float* __restrict__ dst,
                                   int src_ld, int rows) {
    const int gpr = DIMN / 16;  // groups per row = 128
    size_t total = (size_t)rows * gpr;
    for (size_t g = (size_t)blockIdx.x * blockDim.x + threadIdx.x; g < total;
         g += (size_t)gridDim.x * blockDim.x) {
        size_t r = g / gpr;
        int c = (int)(g % gpr);
        const float4* s = reinterpret_cast<const float4*>(src + r * src_ld + c * 16);
        float4 i0 = s[0], i1 = s[1], i2 = s[2], i3 = s[3];
        float4 o0 = make_float4(rna_f(i0.x), rna_f(i1.x), rna_f(i2.x), rna_f(i3.x));
        float4 o1 = make_float4(rna_f(i0.y), rna_f(i1.y), rna_f(i2.y), rna_f(i3.y));
        float4 o2 = make_float4(rna_f(i0.z), rna_f(i1.z), rna_f(i2.z), rna_f(i3.z));
        float4 o3 = make_float4(rna_f(i0.w), rna_f(i1.w), rna_f(i2.w), rna_f(i3.w));
        float4* d = reinterpret_cast<float4*>(dst + r * DIMN + c * 16);
        d[0] = o0; d[1] = o1; d[2] = o2; d[3] = o3;
    }
}

// WPT[j, perm(h)] = rna(w_proj[h, j])
__global__ void transpose_rna_perm_kernel(const float* __restrict__ in,
                                          float* __restrict__ out, int n) {
    __shared__ float t[32][33];
    int x = blockIdx.x * 32 + threadIdx.x;
    int y0 = blockIdx.y * 32;
    for (int i = threadIdx.y; i < 32; i += 8)
        t[i][threadIdx.x] = in[(size_t)(y0 + i) * n + x];
    __syncthreads();
    int xo = blockIdx.y * 32 + threadIdx.x;
    int o = xo & 15;
    int xo_phys = (xo & ~15) | (((o & 3) << 2) | (o >> 2));
    int yo0 = blockIdx.x * 32;
    for (int i = threadIdx.y; i < 32; i += 8)
        out[(size_t)(yo0 + i) * n + xo_phys] = rna_f(t[threadIdx.x][i]);
}

// CB[j] = b_proj[j] + sum_h b_qkv[4096+h] * w_proj[h, j]  (full fp32)
__global__ void bias_kernel(const float* __restrict__ b_qkv,
                            const float* __restrict__ w_proj,
                            const float* __restrict__ b_proj,
                            float* __restrict__ cb) {
    int j = blockIdx.x * blockDim.x + threadIdx.x;
    float acc = b_proj[j];
#pragma unroll 8
    for (int h = 0; h < DIMN; ++h)
        acc += b_qkv[HOFF + h] * w_proj[(size_t)h * DIMN + j];
    cb[j] = acc;
}

// ---------------- tf32 mma.sync GEMM (perm layout, no in-loop cvt) -----------
// out[m,n] = sum_k A[m,k]*B[n,k] (+bias[n]); A,B pre-rounded & 16-group permuted.
// CTA 128x128, 8 warps of 32x64, KT=32 chunks, 3-stage cp.async ring, swizzled.
__device__ __forceinline__ void fill_stage(uint32_t sa,
                                           const float* __restrict__ A,
                                           const float* __restrict__ B,
                                           int m0, int n0, int k0,
                                           int lda, int ldb, int tid) {
    const float* ab = A + (size_t)m0 * lda + k0;
#pragma unroll
    for (int i = tid; i < MT * 8; i += 256) {       // 1024 x 16B
        int row = i >> 3, cw = i & 7;
        cp16(sa + row * 128 + ((cw ^ ((row & 1) << 2)) << 4),
             ab + (size_t)row * lda + cw * 4);
    }
    const float* bb = B + (size_t)n0 * ldb + k0;
    uint32_t sbb = sa + ABYTES;
#pragma unroll
    for (int i = tid; i < NTCTA * 8; i += 256) {
        int row = i >> 3, cw = i & 7;
        cp16(sbb + row * 128 + ((cw ^ ((row & 1) << 2)) << 4),
             bb + (size_t)row * ldb + cw * 4);
    }
}

__device__ __forceinline__ uint32_t frag_addr(uint32_t base, int row, int G, int tig) {
    return base + row * 128 + (((4 * G + tig) ^ ((row & 1) << 2)) << 4);
}

__global__ void __launch_bounds__(256, 2)
gemm_tf32_kernel(const float* __restrict__ A, const float* __restrict__ B,
                 float* __restrict__ out, const float* __restrict__ bias,
                 int K, int lda, int ldb, int ldo) {
    extern __shared__ __align__(16) float smem[];
    const uint32_t sb = smem_u32(smem);

    const int tid = threadIdx.x;
    const int wid = tid >> 5;
    const int lane = tid & 31;
    const int gid = lane >> 2;        // 0..7
    const int tig = lane & 3;         // 0..3
    const int m0 = blockIdx.y * MT;
    const int n0 = blockIdx.x * NTCTA;
    const int moff = (wid & 3) * 32;  // warp M offset
    const int noff = (wid >> 2) * 64; // warp N offset

    float acc[2][8][4];
#pragma unroll
    for (int mt = 0; mt < 2; ++mt)
#pragma unroll
        for (int nt = 0; nt < 8; ++nt)
#pragma unroll
            for (int r = 0; r < 4; ++r) acc[mt][nt][r] = 0.0f;

    const int niter = K / KT;   // 64

    fill_stage(sb, A, B, m0, n0, 0, lda, ldb, tid);
    CP_COMMIT();
    fill_stage(sb + STGB, A, B, m0, n0, KT, lda, ldb, tid);
    CP_COMMIT();

    int s = 0;                       // stage index = it % 3
    for (int it = 0; it < niter; ++it) {
        CP_WAIT1();                  // stage `it` resident for this thread
        __syncthreads();             // all warps done with stage (it-1)

        const int c = it + 2;
        if (c < niter) {
            int sf = s + 2; if (sf >= NSTG) sf -= NSTG;
            fill_stage(sb + sf * STGB, A, B, m0, n0, c * KT, lda, ldb, tid);
        }
        CP_COMMIT();                 // commit every iter (keeps group count uniform)

        const uint32_t sA = sb + s * STGB;
        const uint32_t sB = sA + ABYTES;

#pragma unroll
        for (int G = 0; G < 2; ++G) {   // each G covers two k8 MMA steps
            uint4 af[2][2];
#pragma unroll
            for (int mt = 0; mt < 2; ++mt) {
                int r0 = moff + mt * 16 + gid;
                af[mt][0] = lds128(frag_addr(sA, r0, G, tig));
                af[mt][1] = lds128(frag_addr(sA, r0 + 8, G, tig));
            }
            uint4 bf[8];
#pragma unroll
            for (int nt = 0; nt < 8; ++nt)
                bf[nt] = lds128(frag_addr(sB, noff + nt * 8 + gid, G, tig));
#pragma unroll
            for (int mt = 0; mt < 2; ++mt)
#pragma unroll
                for (int nt = 0; nt < 8; ++nt)
                    mma_tf32(acc[mt][nt], af[mt][0].x, af[mt][1].x,
                             af[mt][0].y, af[mt][1].y, bf[nt].x, bf[nt].y);
#pragma unroll
            for (int mt = 0; mt < 2; ++mt)
#pragma unroll
                for (int nt = 0; nt < 8; ++nt)
                    mma_tf32(acc[mt][nt], af[mt][0].z, af[mt][1].z,
                             af[mt][0].w, af[mt][1].w, bf[nt].z, bf[nt].w);
        }
        if (++s == NSTG) s = 0;
    }

    // epilogue: direct global stores (+bias), plain (unpermuted) output layout
    float2 bb[8];
#pragma unroll
    for (int nt = 0; nt < 8; ++nt) {
        if (bias) {
            bb[nt] = *reinterpret_cast<const float2*>(
                bias + n0 + noff + nt * 8 + tig * 2);
        } else {
            bb[nt].x = 0.0f; bb[nt].y = 0.0f;
        }
    }
#pragma unroll
    for (int mt = 0; mt < 2; ++mt) {
        const int r0 = m0 + moff + mt * 16 + gid;
#pragma unroll
        for (int nt = 0; nt < 8; ++nt) {
            const int col = n0 + noff + nt * 8 + tig * 2;
            float2 v0, v1;
            v0.x = acc[mt][nt][0] + bb[nt].x;
            v0.y = acc[mt][nt][1] + bb[nt].y;
            v1.x = acc[mt][nt][2] + bb[nt].x;
            v1.y = acc[mt][nt][3] + bb[nt].y;
            *reinterpret_cast<float2*>(out + (size_t)r0 * ldo + col) = v0;
            *reinterpret_cast<float2*>(out + (size_t)(r0 + 8) * ldo + col) = v1;
        }
    }
}

// ---------------- host ----------------
extern "C" void kernel_launch(void* const* d_in, const int* in_sizes, int n_in,
                              void* d_out, int out_size) {
    (void)in_sizes; (void)n_in; (void)out_size;
    const float* x     = (const float*)d_in[0];
    const float* wqkv  = (const float*)d_in[1];
    const float* bqkv  = (const float*)d_in[2];
    const float* wproj = (const float*)d_in[3];
    const float* bproj = (const float*)d_in[4];
    float* out = (float*)d_out;

    float *XRP, *WPT, *WVR, *WTraw, *WTP, *CB;
    cudaGetSymbolAddress((void**)&XRP,   g_XRP);
    cudaGetSymbolAddress((void**)&WPT,   g_WPT);
    cudaGetSymbolAddress((void**)&WVR,   g_WVR);
    cudaGetSymbolAddress((void**)&WTraw, g_WTraw);
    cudaGetSymbolAddress((void**)&WTP,   g_WTP);
    cudaGetSymbolAddress((void**)&CB,    g_CB);

    cudaFuncSetAttribute(gemm_tf32_kernel,
                         cudaFuncAttributeMaxDynamicSharedMemorySize, SMEM_DYN);

    // Prepasses: round + permute operands; fold bias
    permute_rna_kernel<<<8192, 256>>>(x, XRP, DIMN, BTOK);
    transpose_rna_perm_kernel<<<dim3(64, 64), dim3(32, 8)>>>(wproj, WPT, DIMN);
    permute_rna_kernel<<<1024, 256>>>(wqkv + HOFF, WVR, QKV3, DIMN);
    bias_kernel<<<8, 256>>>(bqkv, wproj, bproj, CB);

    // WTraw[j,k] = sum_h WPT[j,h] * WVR[k,h]   (= (Wv@Wp)^T)
    gemm_tf32_kernel<<<dim3(DIMN / NTCTA, DIMN / MT), 256, SMEM_DYN>>>(
        WPT, WVR, WTraw, nullptr, DIMN, DIMN, DIMN, DIMN);

    // Round + permute the fused weight for the main GEMM
    permute_rna_kernel<<<1024, 256>>>(WTraw, WTP, DIMN, DIMN);

    // out[b,j] = sum_k XRP[b,k] * WTP[j,k] + CB[j]
    gemm_tf32_kernel<<<dim3(DIMN / NTCTA, BTOK / MT), 256, SMEM_DYN>>>(
        XRP, WTP, out, CB, DIMN, DIMN, DIMN, DIMN);
}

// round 7
// speedup vs baseline: 2.1515x; 1.7854x over previous
#include <cuda_runtime.h>
#include <cuda_fp16.h>
#include <cstdint>

#define DIMN 2048
#define BTOK 16384
#define HOFF 4096
#define QKV3 6144

#define MT 128
#define NTCTA 128
#define KT 32                       /* fp16 elems per chunk = 64 bytes/row */
#define NSTG 4
#define ABYTES (MT * KT * 2)        /* 8192 */
#define STGB (2 * ABYTES)           /* 16384 */
#define SMEM_DYN (NSTG * STGB)      /* 65536 -> 2 CTAs/SM easily */

// Scratch (allocation-free per harness rules)
__device__ __half g_XH[(size_t)BTOK * DIMN];   // fp16+perm(x)       64 MB
__device__ __half g_WPH[(size_t)DIMN * DIMN];  // fp16+perm(Wp^T)     8 MB
__device__ __half g_WVH[(size_t)DIMN * DIMN];  // fp16+perm(Wv)       8 MB
__device__ float  g_WTraw[(size_t)DIMN * DIMN];// (Wv@Wp)^T fp32     16 MB
__device__ __half g_WTH[(size_t)DIMN * DIMN];  // fp16+perm(WTraw)    8 MB
__device__ float  g_BP[32 * DIMN];             // bias partials
__device__ float  g_CB[DIMN];                  // fused bias

// ---------------- helpers ----------------
__device__ __forceinline__ uint32_t smem_u32(const void* p) {
    uint32_t a;
    asm("{ .reg .u64 t; cvta.to.shared.u64 t, %1; cvt.u32.u64 %0, t; }"
        : "=r"(a) : "l"(p));
    return a;
}
__device__ __forceinline__ void cp16(uint32_t dst, const void* src) {
    asm volatile("cp.async.cg.shared.global [%0], [%1], 16;"
                 :: "r"(dst), "l"(src) : "memory");
}
#define CP_COMMIT() asm volatile("cp.async.commit_group;" ::: "memory")
#define CP_WAIT2()  asm volatile("cp.async.wait_group 2;" ::: "memory")

__device__ __forceinline__ uint4 lds128(uint32_t a) {
    uint4 v;
    asm volatile("ld.shared.v4.b32 {%0,%1,%2,%3}, [%4];"
                 : "=r"(v.x), "=r"(v.y), "=r"(v.z), "=r"(v.w) : "r"(a));
    return v;
}
__device__ __forceinline__ void mma_f16(float* d,
                                        uint32_t a0, uint32_t a1, uint32_t a2, uint32_t a3,
                                        uint32_t b0, uint32_t b1) {
    asm volatile(
        "mma.sync.aligned.m16n8k16.row.col.f32.f16.f16.f32 "
        "{%0,%1,%2,%3}, {%4,%5,%6,%7}, {%8,%9}, {%0,%1,%2,%3};"
        : "+f"(d[0]), "+f"(d[1]), "+f"(d[2]), "+f"(d[3])
        : "r"(a0), "r"(a1), "r"(a2), "r"(a3), "r"(b0), "r"(b1));
}

// ---------------- prepass kernels ----------------
// dst row-major fp16, each 32-elem k-group permuted at b32 granularity:
// phys b32 (4t+j) <- logical b32 (t+4j); so one lds128 at 16*t feeds both
// k16 MMA steps of a chunk.
__global__ void pack_h_kernel(const float* __restrict__ src,
                              __half* __restrict__ dst,
                              int src_ld, int rows) {
    const int gpr = DIMN / 32;  // 64 groups per row
    size_t total = (size_t)rows * gpr;
    for (size_t g = (size_t)blockIdx.x * blockDim.x + threadIdx.x; g < total;
         g += (size_t)gridDim.x * blockDim.x) {
        size_t r = g / gpr;
        int c = (int)(g % gpr);
        const float* s = src + r * src_ld + c * 32;
        float f[32];
#pragma unroll
        for (int q = 0; q < 8; ++q) {
            float4 v = reinterpret_cast<const float4*>(s)[q];
            f[q * 4 + 0] = v.x; f[q * 4 + 1] = v.y;
            f[q * 4 + 2] = v.z; f[q * 4 + 3] = v.w;
        }
        __half2 d[16];
#pragma unroll
        for (int p = 0; p < 16; ++p) {
            int t = p >> 2, j = p & 3;
            int l = t + 4 * j;                 // logical b32 (fp16 pair) index
            d[p] = __floats2half2_rn(f[2 * l], f[2 * l + 1]);
        }
        uint4* dd = reinterpret_cast<uint4*>(dst + r * DIMN + c * 32);
        const uint4* ds = reinterpret_cast<const uint4*>(d);
        dd[0] = ds[0]; dd[1] = ds[1]; dd[2] = ds[2]; dd[3] = ds[3];
    }
}

// WPH[j, permphys(h)] = fp16(w_proj[h, j])
__global__ void transpose_h_kernel(const float* __restrict__ in,
                                   __half* __restrict__ out, int n) {
    __shared__ float t[32][33];
    int x = blockIdx.x * 32 + threadIdx.x;
    int y0 = blockIdx.y * 32;
    for (int i = threadIdx.y; i < 32; i += 8)
        t[i][threadIdx.x] = in[(size_t)(y0 + i) * n + x];
    __syncthreads();
    int xo = blockIdx.y * 32 + threadIdx.x;   // logical fp16 col
    int l = (xo & 31) >> 1;                   // logical b32 in group
    int e = xo & 1;
    int tt = l & 3, j = l >> 2;
    int xo_phys = (xo & ~31) | (((4 * tt + j) << 1) | e);
    int yo0 = blockIdx.x * 32;
    for (int i = threadIdx.y; i < 32; i += 8)
        out[(size_t)(yo0 + i) * n + xo_phys] = __float2half_rn(t[threadIdx.x][i]);
}

// bias phase 1: BP[p][j] = sum_{h in [64p,64p+64)} bqkv[4096+h]*wproj[h,j]
__global__ void bias_p1_kernel(const float* __restrict__ b_qkv,
                               const float* __restrict__ w_proj,
                               float* __restrict__ bp) {
    int j = blockIdx.x * blockDim.x + threadIdx.x;
    int h0 = blockIdx.y * 64;
    float acc = 0.0f;
#pragma unroll 8
    for (int h = h0; h < h0 + 64; ++h)
        acc += b_qkv[HOFF + h] * w_proj[(size_t)h * DIMN + j];
    bp[(size_t)blockIdx.y * DIMN + j] = acc;
}
// bias phase 2: CB[j] = bproj[j] + sum_p BP[p][j]
__global__ void bias_p2_kernel(const float* __restrict__ bp,
                               const float* __restrict__ b_proj,
                               float* __restrict__ cb) {
    int j = blockIdx.x * blockDim.x + threadIdx.x;
    float acc = b_proj[j];
#pragma unroll
    for (int p = 0; p < 32; ++p) acc += bp[(size_t)p * DIMN + j];
    cb[j] = acc;
}

// ---------------- fp16 mma.sync GEMM ----------------
// out[m,n] = sum_k A[m,k]*B[n,k] (+bias[n]); A,B fp16, 32-group permuted.
// CTA 128x128, 8 warps of 32x64, KT=32 chunks, 4-stage cp.async ring.
__device__ __forceinline__ void fill_stage(uint32_t sa,
                                           const __half* __restrict__ A,
                                           const __half* __restrict__ B,
                                           int m0, int n0, int k0,
                                           int lda, int ldb, int tid) {
    const __half* ab = A + (size_t)m0 * lda + k0;
#pragma unroll
    for (int i = tid; i < MT * 4; i += 256) {       // 512 x 16B
        int row = i >> 2, cw = i & 3;
        cp16(sa + row * 64 + cw * 16, ab + (size_t)row * lda + cw * 8);
    }
    const __half* bb = B + (size_t)n0 * ldb + k0;
    uint32_t sbb = sa + ABYTES;
#pragma unroll
    for (int i = tid; i < NTCTA * 4; i += 256) {
        int row = i >> 2, cw = i & 3;
        cp16(sbb + row * 64 + cw * 16, bb + (size_t)row * ldb + cw * 8);
    }
}

__global__ void __launch_bounds__(256, 2)
gemm_f16_kernel(const __half* __restrict__ A, const __half* __restrict__ B,
                float* __restrict__ out, const float* __restrict__ bias,
                int K, int lda, int ldb, int ldo) {
    extern __shared__ __align__(16) char smem[];
    const uint32_t sb = smem_u32(smem);

    const int tid = threadIdx.x;
    const int wid = tid >> 5;
    const int lane = tid & 31;
    const int gid = lane >> 2;        // 0..7
    const int tig = lane & 3;         // 0..3
    const int m0 = blockIdx.y * MT;
    const int n0 = blockIdx.x * NTCTA;
    const int moff = (wid & 3) * 32;
    const int noff = (wid >> 2) * 64;

    float acc[2][8][4];
#pragma unroll
    for (int mt = 0; mt < 2; ++mt)
#pragma unroll
        for (int nt = 0; nt < 8; ++nt)
#pragma unroll
            for (int r = 0; r < 4; ++r) acc[mt][nt][r] = 0.0f;

    const int niter = K / KT;   // 64

    fill_stage(sb + 0 * STGB, A, B, m0, n0, 0 * KT, lda, ldb, tid); CP_COMMIT();
    fill_stage(sb + 1 * STGB, A, B, m0, n0, 1 * KT, lda, ldb, tid); CP_COMMIT();
    fill_stage(sb + 2 * STGB, A, B, m0, n0, 2 * KT, lda, ldb, tid); CP_COMMIT();

    int s = 0;
    for (int it = 0; it < niter; ++it) {
        CP_WAIT2();                  // stage `it` resident
        __syncthreads();             // all warps done with stage being refilled

        const int c = it + 3;
        if (c < niter) {
            int sf = s + 3; if (sf >= NSTG) sf -= NSTG;
            fill_stage(sb + sf * STGB, A, B, m0, n0, c * KT, lda, ldb, tid);
        }
        CP_COMMIT();                 // uniform group count per iter

        const uint32_t sA = sb + s * STGB;
        const uint32_t sB = sA + ABYTES;
        const uint32_t co = (uint32_t)(tig * 16);

        // 12 lds128 -> fragments for both k16 steps of this 32-K chunk
        uint4 a0[2], a1[2];
#pragma unroll
        for (int mt = 0; mt < 2; ++mt) {
            int r0 = moff + mt * 16 + gid;
            a0[mt] = lds128(sA + r0 * 64 + co);
            a1[mt] = lds128(sA + (r0 + 8) * 64 + co);
        }
        uint4 bf[8];
#pragma unroll
        for (int nt = 0; nt < 8; ++nt)
            bf[nt] = lds128(sB + (noff + nt * 8 + gid) * 64 + co);

        // step 0 (k 0..15): regs .x (a0/a2 halves in .x/.y), b in .x/.y
#pragma unroll
        for (int mt = 0; mt < 2; ++mt)
#pragma unroll
            for (int nt = 0; nt < 8; ++nt)
                mma_f16(acc[mt][nt], a0[mt].x, a1[mt].x, a0[mt].y, a1[mt].y,
                        bf[nt].x, bf[nt].y);
        // step 1 (k 16..31)
#pragma unroll
        for (int mt = 0; mt < 2; ++mt)
#pragma unroll
            for (int nt = 0; nt < 8; ++nt)
                mma_f16(acc[mt][nt], a0[mt].z, a1[mt].z, a0[mt].w, a1[mt].w,
                        bf[nt].z, bf[nt].w);

        if (++s == NSTG) s = 0;
    }

    // epilogue: direct global stores (+bias)
    float2 bb2[8];
#pragma unroll
    for (int nt = 0; nt < 8; ++nt) {
        if (bias) {
            bb2[nt] = *reinterpret_cast<const float2*>(
                bias + n0 + noff + nt * 8 + tig * 2);
        } else {
            bb2[nt].x = 0.0f; bb2[nt].y = 0.0f;
        }
    }
#pragma unroll
    for (int mt = 0; mt < 2; ++mt) {
        const int r0 = m0 + moff + mt * 16 + gid;
#pragma unroll
        for (int nt = 0; nt < 8; ++nt) {
            const int col = n0 + noff + nt * 8 + tig * 2;
            float2 v0, v1;
            v0.x = acc[mt][nt][0] + bb2[nt].x;
            v0.y = acc[mt][nt][1] + bb2[nt].y;
            v1.x = acc[mt][nt][2] + bb2[nt].x;
            v1.y = acc[mt][nt][3] + bb2[nt].y;
            *reinterpret_cast<float2*>(out + (size_t)r0 * ldo + col) = v0;
            *reinterpret_cast<float2*>(out + (size_t)(r0 + 8) * ldo + col) = v1;
        }
    }
}

// ---------------- host ----------------
extern "C" void kernel_launch(void* const* d_in, const int* in_sizes, int n_in,
                              void* d_out, int out_size) {
    (void)in_sizes; (void)n_in; (void)out_size;
    const float* x     = (const float*)d_in[0];
    const float* wqkv  = (const float*)d_in[1];
    const float* bqkv  = (const float*)d_in[2];
    const float* wproj = (const float*)d_in[3];
    const float* bproj = (const float*)d_in[4];
    float* out = (float*)d_out;

    __half *XH, *WPH, *WVH, *WTH;
    float *WTraw, *BP, *CB;
    cudaGetSymbolAddress((void**)&XH,    g_XH);
    cudaGetSymbolAddress((void**)&WPH,   g_WPH);
    cudaGetSymbolAddress((void**)&WVH,   g_WVH);
    cudaGetSymbolAddress((void**)&WTH,   g_WTH);
    cudaGetSymbolAddress((void**)&WTraw, g_WTraw);
    cudaGetSymbolAddress((void**)&BP,    g_BP);
    cudaGetSymbolAddress((void**)&CB,    g_CB);

    cudaFuncSetAttribute(gemm_f16_kernel,
                         cudaFuncAttributeMaxDynamicSharedMemorySize, SMEM_DYN);

    // Prepasses: pack to fp16+perm; fold bias (two-phase, deterministic)
    pack_h_kernel<<<4096, 256>>>(x, XH, DIMN, BTOK);
    transpose_h_kernel<<<dim3(64, 64), dim3(32, 8)>>>(wproj, WPH, DIMN);
    pack_h_kernel<<<512, 256>>>(wqkv + HOFF, WVH, QKV3, DIMN);
    bias_p1_kernel<<<dim3(8, 32), 256>>>(bqkv, wproj, BP);
    bias_p2_kernel<<<8, 256>>>(BP, bproj, CB);

    // WTraw[j,k] = sum_h WPH[j,h] * WVH[k,h]   (= (Wv@Wp)^T), fp32 out
    gemm_f16_kernel<<<dim3(DIMN / NTCTA, DIMN / MT), 256, SMEM_DYN>>>(
        WPH, WVH, WTraw, nullptr, DIMN, DIMN, DIMN, DIMN);

    // pack fused weight for main GEMM
    pack_h_kernel<<<512, 256>>>(WTraw, WTH, DIMN, DIMN);

    // out[b,j] = sum_k XH[b,k] * WTH[j,k] + CB[j]
    gemm_f16_kernel<<<dim3(DIMN / NTCTA, BTOK / MT), 256, SMEM_DYN>>>(
        XH, WTH, out, CB, DIMN, DIMN, DIMN, DIMN);
}

// round 8
// speedup vs baseline: 2.5197x; 1.1712x over previous
#include <cuda_runtime.h>
#include <cuda_fp16.h>
#include <cstdint>

#define DIMN 2048
#define BTOK 16384
#define HOFF 4096
#define QKV3 6144

#define MT 128                      /* CTA tile M */
#define NTCTA 256                   /* CTA tile N */
#define KT 64                       /* fp16 elems per chunk = 128 B/row */
#define NSTG 4
#define ABYTES (MT * KT * 2)        /* 16384 */
#define BBYTES (NTCTA * KT * 2)     /* 32768 */
#define STGB (ABYTES + BBYTES)      /* 49152 */
#define SMEM_DYN (NSTG * STGB)      /* 196608 */

// Scratch (allocation-free per harness rules)
__device__ __half g_XH[(size_t)BTOK * DIMN];   // fp16+perm(x)       64 MB
__device__ __half g_WPH[(size_t)DIMN * DIMN];  // fp16+perm(Wp^T)     8 MB
__device__ __half g_WVH[(size_t)DIMN * DIMN];  // fp16+perm(Wv)       8 MB
__device__ float  g_WTraw[(size_t)DIMN * DIMN];// (Wv@Wp)^T fp32     16 MB
__device__ __half g_WTH[(size_t)DIMN * DIMN];  // fp16+perm(WTraw)    8 MB
__device__ float  g_BP[32 * DIMN];             // bias partials
__device__ float  g_CB[DIMN];                  // fused bias

// ---------------- helpers ----------------
__device__ __forceinline__ uint32_t smem_u32(const void* p) {
    uint32_t a;
    asm("{ .reg .u64 t; cvta.to.shared.u64 t, %1; cvt.u32.u64 %0, t; }"
        : "=r"(a) : "l"(p));
    return a;
}
__device__ __forceinline__ void cp16(uint32_t dst, const void* src) {
    asm volatile("cp.async.cg.shared.global [%0], [%1], 16;"
                 :: "r"(dst), "l"(src) : "memory");
}
#define CP_COMMIT() asm volatile("cp.async.commit_group;" ::: "memory")
#define CP_WAIT2()  asm volatile("cp.async.wait_group 2;" ::: "memory")

__device__ __forceinline__ uint4 lds128(uint32_t a) {
    uint4 v;
    asm volatile("ld.shared.v4.b32 {%0,%1,%2,%3}, [%4];"
                 : "=r"(v.x), "=r"(v.y), "=r"(v.z), "=r"(v.w) : "r"(a));
    return v;
}
__device__ __forceinline__ void mma_f16(float* d,
                                        uint32_t a0, uint32_t a1, uint32_t a2, uint32_t a3,
                                        uint32_t b0, uint32_t b1) {
    asm volatile(
        "mma.sync.aligned.m16n8k16.row.col.f32.f16.f16.f32 "
        "{%0,%1,%2,%3}, {%4,%5,%6,%7}, {%8,%9}, {%0,%1,%2,%3};"
        : "+f"(d[0]), "+f"(d[1]), "+f"(d[2]), "+f"(d[3])
        : "r"(a0), "r"(a1), "r"(a2), "r"(a3), "r"(b0), "r"(b1));
}

// ---------------- prepass kernels ----------------
// dst row-major fp16, each 32-elem k-group permuted at b32 granularity:
// phys b32 (4t+j) <- logical b32 (t+4j).
__global__ void pack_h_kernel(const float* __restrict__ src,
                              __half* __restrict__ dst,
                              int src_ld, int rows) {
    const int gpr = DIMN / 32;  // 64 groups per row
    size_t total = (size_t)rows * gpr;
    for (size_t g = (size_t)blockIdx.x * blockDim.x + threadIdx.x; g < total;
         g += (size_t)gridDim.x * blockDim.x) {
        size_t r = g / gpr;
        int c = (int)(g % gpr);
        const float* s = src + r * src_ld + c * 32;
        float f[32];
#pragma unroll
        for (int q = 0; q < 8; ++q) {
            float4 v = reinterpret_cast<const float4*>(s)[q];
            f[q * 4 + 0] = v.x; f[q * 4 + 1] = v.y;
            f[q * 4 + 2] = v.z; f[q * 4 + 3] = v.w;
        }
        __half2 d[16];
#pragma unroll
        for (int p = 0; p < 16; ++p) {
            int t = p >> 2, j = p & 3;
            int l = t + 4 * j;
            d[p] = __floats2half2_rn(f[2 * l], f[2 * l + 1]);
        }
        uint4* dd = reinterpret_cast<uint4*>(dst + r * DIMN + c * 32);
        const uint4* ds = reinterpret_cast<const uint4*>(d);
        dd[0] = ds[0]; dd[1] = ds[1]; dd[2] = ds[2]; dd[3] = ds[3];
    }
}

// WPH[j, permphys(h)] = fp16(w_proj[h, j])
__global__ void transpose_h_kernel(const float* __restrict__ in,
                                   __half* __restrict__ out, int n) {
    __shared__ float t[32][33];
    int x = blockIdx.x * 32 + threadIdx.x;
    int y0 = blockIdx.y * 32;
    for (int i = threadIdx.y; i < 32; i += 8)
        t[i][threadIdx.x] = in[(size_t)(y0 + i) * n + x];
    __syncthreads();
    int xo = blockIdx.y * 32 + threadIdx.x;
    int l = (xo & 31) >> 1;
    int e = xo & 1;
    int tt = l & 3, j = l >> 2;
    int xo_phys = (xo & ~31) | (((4 * tt + j) << 1) | e);
    int yo0 = blockIdx.x * 32;
    for (int i = threadIdx.y; i < 32; i += 8)
        out[(size_t)(yo0 + i) * n + xo_phys] = __float2half_rn(t[threadIdx.x][i]);
}

__global__ void bias_p1_kernel(const float* __restrict__ b_qkv,
                               const float* __restrict__ w_proj,
                               float* __restrict__ bp) {
    int j = blockIdx.x * blockDim.x + threadIdx.x;
    int h0 = blockIdx.y * 64;
    float acc = 0.0f;
#pragma unroll 8
    for (int h = h0; h < h0 + 64; ++h)
        acc += b_qkv[HOFF + h] * w_proj[(size_t)h * DIMN + j];
    bp[(size_t)blockIdx.y * DIMN + j] = acc;
}
__global__ void bias_p2_kernel(const float* __restrict__ bp,
                               const float* __restrict__ b_proj,
                               float* __restrict__ cb) {
    int j = blockIdx.x * blockDim.x + threadIdx.x;
    float acc = b_proj[j];
#pragma unroll
    for (int p = 0; p < 32; ++p) acc += bp[(size_t)p * DIMN + j];
    cb[j] = acc;
}

// ---------------- fp16 mma.sync GEMM ----------------
// out[m,n] = sum_k A[m,k]*B[n,k] (+bias[n]); A,B fp16, 32-group permuted.
// CTA 128x256, 8 warps of 64x64, KT=64 chunks, 4-stage cp.async ring.
// SMEM rows are 128 B (two 64 B perm-groups); group halves XOR-swizzled by
// row parity so LDS128 phases are bank-conflict-free.
__device__ __forceinline__ void fill_stage(uint32_t sa,
                                           const __half* __restrict__ A,
                                           const __half* __restrict__ B,
                                           int m0, int n0, int k0,
                                           int lda, int ldb, int tid) {
    const __half* ab = A + (size_t)m0 * lda + k0;
#pragma unroll
    for (int i = tid; i < MT * 8; i += 256) {        // 1024 x 16B
        int row = i >> 3, cw = i & 7;
        cp16(sa + row * 128 + ((cw ^ ((row & 1) << 2)) << 4),
             ab + (size_t)row * lda + cw * 8);
    }
    const __half* bb = B + (size_t)n0 * ldb + k0;
    uint32_t sbb = sa + ABYTES;
#pragma unroll
    for (int i = tid; i < NTCTA * 8; i += 256) {     // 2048 x 16B
        int row = i >> 3, cw = i & 7;
        cp16(sbb + row * 128 + ((cw ^ ((row & 1) << 2)) << 4),
             bb + (size_t)row * ldb + cw * 8);
    }
}

__device__ __forceinline__ uint32_t frag_addr(uint32_t base, int row, int g, int tig) {
    return base + row * 128 + ((((g << 2) | tig) ^ ((row & 1) << 2)) << 4);
}

__global__ void __launch_bounds__(256, 1)
gemm_f16_kernel(const __half* __restrict__ A, const __half* __restrict__ B,
                float* __restrict__ out, const float* __restrict__ bias,
                int K, int lda, int ldb, int ldo) {
    extern __shared__ __align__(16) char smem[];
    const uint32_t sb = smem_u32(smem);

    const int tid = threadIdx.x;
    const int wid = tid >> 5;
    const int lane = tid & 31;
    const int gid = lane >> 2;        // 0..7
    const int tig = lane & 3;         // 0..3
    const int m0 = blockIdx.y * MT;
    const int n0 = blockIdx.x * NTCTA;
    const int moff = (wid & 1) * 64;  // warp M offset (2 m-warps)
    const int noff = (wid >> 1) * 64; // warp N offset (4 n-warps)

    float acc[4][8][4];
#pragma unroll
    for (int mt = 0; mt < 4; ++mt)
#pragma unroll
        for (int nt = 0; nt < 8; ++nt)
#pragma unroll
            for (int r = 0; r < 4; ++r) acc[mt][nt][r] = 0.0f;

    const int niter = K / KT;   // 32

    fill_stage(sb + 0 * STGB, A, B, m0, n0, 0 * KT, lda, ldb, tid); CP_COMMIT();
    fill_stage(sb + 1 * STGB, A, B, m0, n0, 1 * KT, lda, ldb, tid); CP_COMMIT();
    fill_stage(sb + 2 * STGB, A, B, m0, n0, 2 * KT, lda, ldb, tid); CP_COMMIT();

    int s = 0;
    for (int it = 0; it < niter; ++it) {
        CP_WAIT2();                  // stage `it` resident
        __syncthreads();             // all warps done with the stage being refilled

        const int c = it + 3;
        if (c < niter) {
            int sf = s + 3; if (sf >= NSTG) sf -= NSTG;
            fill_stage(sb + sf * STGB, A, B, m0, n0, c * KT, lda, ldb, tid);
        }
        CP_COMMIT();                 // uniform group count per iter

        const uint32_t sA = sb + s * STGB;
        const uint32_t sB = sA + ABYTES;

#pragma unroll
        for (int g = 0; g < 2; ++g) {    // each group covers two k16 steps
            uint4 a0[4], a1[4];
#pragma unroll
            for (int mt = 0; mt < 4; ++mt) {
                int r0 = moff + mt * 16 + gid;
                a0[mt] = lds128(frag_addr(sA, r0, g, tig));
                a1[mt] = lds128(frag_addr(sA, r0 + 8, g, tig));
            }
            uint4 bf[8];
#pragma unroll
            for (int nt = 0; nt < 8; ++nt)
                bf[nt] = lds128(frag_addr(sB, noff + nt * 8 + gid, g, tig));

            // k16 step even: .x/.y
#pragma unroll
            for (int mt = 0; mt < 4; ++mt)
#pragma unroll
                for (int nt = 0; nt < 8; ++nt)
                    mma_f16(acc[mt][nt], a0[mt].x, a1[mt].x, a0[mt].y, a1[mt].y,
                            bf[nt].x, bf[nt].y);
            // k16 step odd: .z/.w
#pragma unroll
            for (int mt = 0; mt < 4; ++mt)
#pragma unroll
                for (int nt = 0; nt < 8; ++nt)
                    mma_f16(acc[mt][nt], a0[mt].z, a1[mt].z, a0[mt].w, a1[mt].w,
                            bf[nt].z, bf[nt].w);
        }
        if (++s == NSTG) s = 0;
    }

    // epilogue: direct global stores (+bias)
    float2 bb2[8];
#pragma unroll
    for (int nt = 0; nt < 8; ++nt) {
        if (bias) {
            bb2[nt] = *reinterpret_cast<const float2*>(
                bias + n0 + noff + nt * 8 + tig * 2);
        } else {
            bb2[nt].x = 0.0f; bb2[nt].y = 0.0f;
        }
    }
#pragma unroll
    for (int mt = 0; mt < 4; ++mt) {
        const int r0 = m0 + moff + mt * 16 + gid;
#pragma unroll
        for (int nt = 0; nt < 8; ++nt) {
            const int col = n0 + noff + nt * 8 + tig * 2;
            float2 v0, v1;
            v0.x = acc[mt][nt][0] + bb2[nt].x;
            v0.y = acc[mt][nt][1] + bb2[nt].y;
            v1.x = acc[mt][nt][2] + bb2[nt].x;
            v1.y = acc[mt][nt][3] + bb2[nt].y;
            *reinterpret_cast<float2*>(out + (size_t)r0 * ldo + col) = v0;
            *reinterpret_cast<float2*>(out + (size_t)(r0 + 8) * ldo + col) = v1;
        }
    }
}

// ---------------- host ----------------
extern "C" void kernel_launch(void* const* d_in, const int* in_sizes, int n_in,
                              void* d_out, int out_size) {
    (void)in_sizes; (void)n_in; (void)out_size;
    const float* x     = (const float*)d_in[0];
    const float* wqkv  = (const float*)d_in[1];
    const float* bqkv  = (const float*)d_in[2];
    const float* wproj = (const float*)d_in[3];
    const float* bproj = (const float*)d_in[4];
    float* out = (float*)d_out;

    __half *XH, *WPH, *WVH, *WTH;
    float *WTraw, *BP, *CB;
    cudaGetSymbolAddress((void**)&XH,    g_XH);
    cudaGetSymbolAddress((void**)&WPH,   g_WPH);
    cudaGetSymbolAddress((void**)&WVH,   g_WVH);
    cudaGetSymbolAddress((void**)&WTH,   g_WTH);
    cudaGetSymbolAddress((void**)&WTraw, g_WTraw);
    cudaGetSymbolAddress((void**)&BP,    g_BP);
    cudaGetSymbolAddress((void**)&CB,    g_CB);

    cudaFuncSetAttribute(gemm_f16_kernel,
                         cudaFuncAttributeMaxDynamicSharedMemorySize, SMEM_DYN);

    // Prepasses: pack to fp16+perm; fold bias (two-phase, deterministic)
    pack_h_kernel<<<4096, 256>>>(x, XH, DIMN, BTOK);
    transpose_h_kernel<<<dim3(64, 64), dim3(32, 8)>>>(wproj, WPH, DIMN);
    pack_h_kernel<<<512, 256>>>(wqkv + HOFF, WVH, QKV3, DIMN);
    bias_p1_kernel<<<dim3(8, 32), 256>>>(bqkv, wproj, BP);
    bias_p2_kernel<<<8, 256>>>(BP, bproj, CB);

    // WTraw[j,k] = sum_h WPH[j,h] * WVH[k,h]   (= (Wv@Wp)^T), fp32 out
    gemm_f16_kernel<<<dim3(DIMN / NTCTA, DIMN / MT), 256, SMEM_DYN>>>(
        WPH, WVH, WTraw, nullptr, DIMN, DIMN, DIMN, DIMN);

    // pack fused weight for main GEMM
    pack_h_kernel<<<512, 256>>>(WTraw, WTH, DIMN, DIMN);

    // out[b,j] = sum_k XH[b,k] * WTH[j,k] + CB[j]
    gemm_f16_kernel<<<dim3(DIMN / NTCTA, BTOK / MT), 256, SMEM_DYN>>>(
        XH, WTH, out, CB, DIMN, DIMN, DIMN, DIMN);
}